// round 3
// baseline (speedup 1.0000x reference)
#include <cuda_runtime.h>
#include <cuda_bf16.h>

// KAN layer: y[b,o] = sum_f lerp(coeff[f, idx-1, o], coeff[f, idx, o], t) + bias[o]
// B=4096, F=128, G=64, OUT=64.  grid = linspace(-3,3,64), h = 6/63, inv_h = 10.5
// searchsorted 'left' clipped to [1,63]: i = clip(ceil((x+3)*10.5), 1, 63)
// t = (x+3)*10.5 - (i-1)   (unclamped: reference extrapolates)
//
// R2: (a) precompute (row-offset, t) per (b,f) once into smem (kills 16x
// replicated index ALU, shortens dep chain); (b) explicit 4-feature load
// batching (MLP~8) with a 64-reg cap instead of a 32-reg squeeze.

#define F_DIM   128
#define G_SIZE  64
#define OUT_N   64
#define SPB     4                   // samples per block
#define FGROUPS 4
#define F_PER_T (F_DIM / FGROUPS)   // 32
#define THREADS 256
#define BATCH   4

__global__ __launch_bounds__(THREADS, 4)
void kan_pre_kernel(const float* __restrict__ x,
                    const float* __restrict__ coeff,
                    const float* __restrict__ bias,
                    float* __restrict__ y)
{
    __shared__ float  xs[SPB * F_DIM];        // 2 KB
    __shared__ float2 sidx[SPB * F_DIM];      // 4 KB: (.x = row offset bits, .y = t)
    __shared__ float4 part[THREADS];          // 4 KB

    const int tid  = threadIdx.x;
    const int row0 = blockIdx.x * SPB;

    // ---- Phase 0: x tile (512 floats = 128 float4) ----
    if (tid < SPB * F_DIM / 4) {
        reinterpret_cast<float4*>(xs)[tid] =
            reinterpret_cast<const float4*>(x + row0 * F_DIM)[tid];
    }
    __syncthreads();

    // ---- Phase 1: per-(s,f) index/t, computed ONCE (2 pairs per thread) ----
    {
        const float inv_h = 10.5f;   // 63/6
        #pragma unroll
        for (int k = 0; k < (SPB * F_DIM) / THREADS; ++k) {
            const int p  = tid + k * THREADS;       // p = s*F_DIM + f
            const float u = (xs[p] + 3.0f) * inv_h;
            int i = (int)ceilf(u);
            i = max(1, min(i, G_SIZE - 1));
            const float t = u - (float)(i - 1);
            const int f = p & (F_DIM - 1);
            const int off = (f * G_SIZE + (i - 1)) * OUT_N;   // element offset of row i-1
            sidx[p] = make_float2(__int_as_float(off), t);
        }
    }
    __syncthreads();

    // ---- Phase 2: gather + lerp + accumulate ----
    const int lane = tid & 15;          // output slice (4 floats)
    const int fg   = (tid >> 4) & 3;    // feature group
    const int s    = tid >> 6;          // local sample
    const int o4   = lane << 2;

    const float2* sp = sidx + s * F_DIM + fg * F_PER_T;
    const float*  cb = coeff + o4;

    float4 acc = make_float4(0.f, 0.f, 0.f, 0.f);

    for (int f0 = 0; f0 < F_PER_T; f0 += BATCH) {
        float4 c0[BATCH], c1[BATCH];
        float  tt[BATCH];

        #pragma unroll
        for (int j = 0; j < BATCH; ++j) {
            const float2 bt = sp[f0 + j];
            tt[j] = bt.y;
            const float* p = cb + __float_as_int(bt.x);
            c0[j] = *reinterpret_cast<const float4*>(p);
            c1[j] = *reinterpret_cast<const float4*>(p + OUT_N);
        }

        #pragma unroll
        for (int j = 0; j < BATCH; ++j) {
            acc.x += c0[j].x + tt[j] * (c1[j].x - c0[j].x);
            acc.y += c0[j].y + tt[j] * (c1[j].y - c0[j].y);
            acc.z += c0[j].z + tt[j] * (c1[j].z - c0[j].z);
            acc.w += c0[j].w + tt[j] * (c1[j].w - c0[j].w);
        }
    }

    part[tid] = acc;
    __syncthreads();

    // ---- Phase 3: reduce the 4 feature-group partials, add bias, store ----
    if (fg == 0) {
        const float4 p1 = part[tid + 16];
        const float4 p2 = part[tid + 32];
        const float4 p3 = part[tid + 48];
        const float4 bv = *reinterpret_cast<const float4*>(bias + o4);

        acc.x += p1.x + p2.x + p3.x + bv.x;
        acc.y += p1.y + p2.y + p3.y + bv.y;
        acc.z += p1.z + p2.z + p3.z + bv.z;
        acc.w += p1.w + p2.w + p3.w + bv.w;

        *reinterpret_cast<float4*>(y + (row0 + s) * OUT_N + o4) = acc;
    }
}

extern "C" void kernel_launch(void* const* d_in, const int* in_sizes, int n_in,
                              void* d_out, int out_size)
{
    const float* x     = (const float*)d_in[0];   // [4096, 128]
    const float* coeff = (const float*)d_in[1];   // [128, 64, 64]
    const float* bias  = (const float*)d_in[2];   // [64]
    float* y           = (float*)d_out;           // [4096, 64]

    const int n_samples = in_sizes[0] / F_DIM;    // 4096
    const int blocks = n_samples / SPB;           // 1024

    kan_pre_kernel<<<blocks, THREADS>>>(x, coeff, bias, y);
}